// round 1
// baseline (speedup 1.0000x reference)
#include <cuda_runtime.h>

// Net0: x[B,2] -> Linear(2,7)+ELU -> 19x (Linear(7,7)+ELU) -> Linear(7,2) -> log_softmax
// B = 4,194,304. All fp32. Compute-bound on the FMA pipe (~960 FMA/row).

constexpr int H     = 7;
constexpr int NMID  = 19;
constexpr int THREADS = 256;

__device__ __forceinline__ float elu_f(float v) {
    // jax.nn.elu: x>0 ? x : expm1(x). exp(x)-1 via MUFU is accurate enough
    // (abs err ~1e-7 at small |x|; final tolerance is 1e-3 on log_softmax output).
    float e = __expf(v) - 1.0f;
    return v > 0.0f ? v : e;
}

__global__ void __launch_bounds__(THREADS)
net0_kernel(const float* __restrict__ x,
            const float* __restrict__ W1, const float* __restrict__ b1,
            const float* __restrict__ Wm, const float* __restrict__ bm,
            const float* __restrict__ Wo, const float* __restrict__ bo,
            float* __restrict__ out, int B)
{
    // Stage all weights in shared memory (4.4 KB). Broadcast LDS is conflict-free
    // and interleaves into FFMA rt-2 issue gaps for free.
    __shared__ float sW1[H * 2];
    __shared__ float sb1[H];
    __shared__ float sWm[NMID * H * H];
    __shared__ float sbm[NMID * H];
    __shared__ float sWo[2 * H];
    __shared__ float sbo[2];

    for (int i = threadIdx.x; i < H * 2;        i += THREADS) sW1[i] = W1[i];
    for (int i = threadIdx.x; i < H;            i += THREADS) sb1[i] = b1[i];
    for (int i = threadIdx.x; i < NMID * H * H; i += THREADS) sWm[i] = Wm[i];
    for (int i = threadIdx.x; i < NMID * H;     i += THREADS) sbm[i] = bm[i];
    for (int i = threadIdx.x; i < 2 * H;        i += THREADS) sWo[i] = Wo[i];
    for (int i = threadIdx.x; i < 2;            i += THREADS) sbo[i] = bo[i];
    __syncthreads();

    int row = blockIdx.x * THREADS + threadIdx.x;
    if (row >= B) return;

    // Coalesced float2 load of the input row.
    float2 xv = reinterpret_cast<const float2*>(x)[row];

    float h[H];

    // fc1 + ELU
#pragma unroll
    for (int i = 0; i < H; i++) {
        float acc = sb1[i];
        acc = fmaf(xv.x, sW1[i * 2 + 0], acc);
        acc = fmaf(xv.y, sW1[i * 2 + 1], acc);
        h[i] = elu_f(acc);
    }

    // fc2..fc20: keep the layer loop ROLLED so the body (~2KB SASS) stays in L0 I$.
#pragma unroll 1
    for (int l = 0; l < NMID; l++) {
        const float* w = &sWm[l * H * H];
        const float* b = &sbm[l * H];
        float hn[H];
#pragma unroll
        for (int i = 0; i < H; i++) {
            float acc = b[i];
#pragma unroll
            for (int j = 0; j < H; j++)
                acc = fmaf(w[i * H + j], h[j], acc);
            hn[i] = acc;
        }
#pragma unroll
        for (int i = 0; i < H; i++) h[i] = elu_f(hn[i]);
    }

    // fc21 + log_softmax (2-way)
    float l0 = sbo[0], l1 = sbo[1];
#pragma unroll
    for (int j = 0; j < H; j++) {
        l0 = fmaf(sWo[0 * H + j], h[j], l0);
        l1 = fmaf(sWo[1 * H + j], h[j], l1);
    }
    float m   = fmaxf(l0, l1);
    float lse = m + __logf(__expf(l0 - m) + __expf(l1 - m));

    reinterpret_cast<float2*>(out)[row] = make_float2(l0 - lse, l1 - lse);
}

extern "C" void kernel_launch(void* const* d_in, const int* in_sizes, int n_in,
                              void* d_out, int out_size)
{
    const float* x  = (const float*)d_in[0];
    const float* W1 = (const float*)d_in[1];
    const float* b1 = (const float*)d_in[2];
    const float* Wm = (const float*)d_in[3];
    const float* bm = (const float*)d_in[4];
    const float* Wo = (const float*)d_in[5];
    const float* bo = (const float*)d_in[6];
    float* out = (float*)d_out;

    int B = in_sizes[0] / 2;  // x is [B,2]
    int grid = (B + THREADS - 1) / THREADS;
    net0_kernel<<<grid, THREADS>>>(x, W1, b1, Wm, bm, Wo, bo, out, B);
}

// round 2
// speedup vs baseline: 1.6429x; 1.6429x over previous
#include <cuda_runtime.h>

// Net0: x[B,2] -> fc1(2,7)+ELU -> 19x fc(7,7)+ELU -> fc(7,2) -> log_softmax.
// R2 strategy: 2 rows/thread, packed fma.rn.f32x2 (FFMA2), weights duplicated
// (w,w) in shared so LDS.128 delivers two packed broadcast operands directly.

constexpr int H       = 7;
constexpr int NMID    = 19;
constexpr int THREADS = 256;
// per-layer shared layout: for each i (output neuron): 8 float2 slots
//   k=0..6 : (Wm[l][i][k], Wm[l][i][k])   duplicated weight
//   k=7    : (bm[l][i],    bm[l][i])      duplicated bias
// stride per i = 64B (4 x 16B), per layer = 56 float2 = 448B (16B aligned)
constexpr int LSTRIDE = 56;

typedef unsigned long long u64;

__device__ __forceinline__ u64 pack2(float lo, float hi) {
    u64 r; asm("mov.b64 %0, {%1, %2};" : "=l"(r) : "f"(lo), "f"(hi)); return r;
}
__device__ __forceinline__ void unpack2(u64 v, float& lo, float& hi) {
    asm("mov.b64 {%0, %1}, %2;" : "=f"(lo), "=f"(hi) : "l"(v));
}
__device__ __forceinline__ u64 fma2(u64 a, u64 b, u64 c) {
    u64 d; asm("fma.rn.f32x2 %0, %1, %2, %3;" : "=l"(d) : "l"(a), "l"(b), "l"(c));
    return d;
}
__device__ __forceinline__ float elu1(float v) {
    float e = __expf(v) - 1.0f;          // FMUL + MUFU.EX2 + FADD
    return v > 0.0f ? v : e;             // FSETP + FSEL
}
__device__ __forceinline__ u64 elu2(u64 v) {
    float lo, hi; unpack2(v, lo, hi);
    return pack2(elu1(lo), elu1(hi));
}

__global__ void __launch_bounds__(THREADS)
net0_kernel(const float* __restrict__ x,
            const float* __restrict__ W1, const float* __restrict__ b1,
            const float* __restrict__ Wm, const float* __restrict__ bm,
            const float* __restrict__ Wo, const float* __restrict__ bo,
            float* __restrict__ out, int nPairs)
{
    __shared__ __align__(16) float2 sFc1[H * 4];        // per i: {w0d, w1d, bd, pad}
    __shared__ __align__(16) float2 sMid[NMID * LSTRIDE];
    __shared__ __align__(16) float2 sFcO[2 * 8];        // per r: 7 wd + bias d

    // ---- cooperative duplicated-weight staging ----
    for (int idx = threadIdx.x; idx < H * 4; idx += THREADS) {
        int i = idx >> 2, k = idx & 3;
        float v = (k < 2) ? W1[i * 2 + k] : (k == 2 ? b1[i] : 0.0f);
        sFc1[idx] = make_float2(v, v);
    }
    for (int idx = threadIdx.x; idx < NMID * H * 8; idx += THREADS) {
        int l = idx / (H * 8);
        int r = idx - l * (H * 8);
        int i = r >> 3, k = r & 7;
        float v = (k < 7) ? Wm[(l * H + i) * H + k] : bm[l * H + i];
        sMid[l * LSTRIDE + i * 8 + k] = make_float2(v, v);
    }
    for (int idx = threadIdx.x; idx < 16; idx += THREADS) {
        int r = idx >> 3, k = idx & 7;
        float v = (k < 7) ? Wo[r * H + k] : bo[r];
        sFcO[idx] = make_float2(v, v);
    }
    __syncthreads();

    int pair = blockIdx.x * THREADS + threadIdx.x;   // 2 rows per thread
    if (pair >= nPairs) return;

    // coalesced 16B load: (row0.x, row0.y, row1.x, row1.y)
    float4 xin = reinterpret_cast<const float4*>(x)[pair];
    u64 xp0 = pack2(xin.x, xin.z);   // feature 0, both rows
    u64 xp1 = pack2(xin.y, xin.w);   // feature 1, both rows

    u64 h[H];

    // ---- fc1 + ELU ----
#pragma unroll
    for (int i = 0; i < H; i++) {
        const ulonglong2* p = reinterpret_cast<const ulonglong2*>(&sFc1[i * 4]);
        ulonglong2 a = p[0];   // {w0 dup, w1 dup}
        ulonglong2 b = p[1];   // {bias dup, pad}
        h[i] = elu2(fma2(a.x, xp0, fma2(a.y, xp1, b.x)));
    }

    // ---- fc2..fc20 : rolled layer loop (small SASS body, stays in L0 I$) ----
#pragma unroll 1
    for (int l = 0; l < NMID; l++) {
        const ulonglong2* base =
            reinterpret_cast<const ulonglong2*>(&sMid[l * LSTRIDE]);
        u64 hn[H];
#pragma unroll
        for (int i = 0; i < H; i++) {
            ulonglong2 q0 = base[i * 4 + 0];   // w0,w1
            ulonglong2 q1 = base[i * 4 + 1];   // w2,w3
            ulonglong2 q2 = base[i * 4 + 2];   // w4,w5
            ulonglong2 q3 = base[i * 4 + 3];   // w6,bias
            u64 acc = q3.y;
            acc = fma2(q0.x, h[0], acc);
            acc = fma2(q0.y, h[1], acc);
            acc = fma2(q1.x, h[2], acc);
            acc = fma2(q1.y, h[3], acc);
            acc = fma2(q2.x, h[4], acc);
            acc = fma2(q2.y, h[5], acc);
            acc = fma2(q3.x, h[6], acc);
            hn[i] = acc;
        }
#pragma unroll
        for (int i = 0; i < H; i++) h[i] = elu2(hn[i]);
    }

    // ---- fc21 (2 logits, packed across rows) ----
    u64 lp[2];
#pragma unroll
    for (int r = 0; r < 2; r++) {
        const ulonglong2* p = reinterpret_cast<const ulonglong2*>(&sFcO[r * 8]);
        ulonglong2 q0 = p[0], q1 = p[1], q2 = p[2], q3 = p[3];
        u64 acc = q3.y;
        acc = fma2(q0.x, h[0], acc);
        acc = fma2(q0.y, h[1], acc);
        acc = fma2(q1.x, h[2], acc);
        acc = fma2(q1.y, h[3], acc);
        acc = fma2(q2.x, h[4], acc);
        acc = fma2(q2.y, h[5], acc);
        acc = fma2(q3.x, h[6], acc);
        lp[r] = acc;
    }

    float l0a, l0b, l1a, l1b;
    unpack2(lp[0], l0a, l0b);
    unpack2(lp[1], l1a, l1b);

    // log_softmax over 2 classes, per row
    float m0   = fmaxf(l0a, l1a);
    float lse0 = m0 + __logf(__expf(l0a - m0) + __expf(l1a - m0));
    float m1   = fmaxf(l0b, l1b);
    float lse1 = m1 + __logf(__expf(l0b - m1) + __expf(l1b - m1));

    float4 o;
    o.x = l0a - lse0;  o.y = l1a - lse0;   // row 0
    o.z = l0b - lse1;  o.w = l1b - lse1;   // row 1
    reinterpret_cast<float4*>(out)[pair] = o;
}

extern "C" void kernel_launch(void* const* d_in, const int* in_sizes, int n_in,
                              void* d_out, int out_size)
{
    const float* x  = (const float*)d_in[0];
    const float* W1 = (const float*)d_in[1];
    const float* b1 = (const float*)d_in[2];
    const float* Wm = (const float*)d_in[3];
    const float* bm = (const float*)d_in[4];
    const float* Wo = (const float*)d_in[5];
    const float* bo = (const float*)d_in[6];
    float* out = (float*)d_out;

    int nPairs = in_sizes[0] / 4;            // x is [B,2], 2 rows per thread
    int grid = (nPairs + THREADS - 1) / THREADS;
    net0_kernel<<<grid, THREADS>>>(x, W1, b1, Wm, bm, Wo, bo, out, nPairs);
}

// round 3
// speedup vs baseline: 1.7749x; 1.0803x over previous
#include <cuda_runtime.h>

// Net0: x[B,2] -> fc1(2,7)+ELU -> 19x fc(7,7)+ELU -> fc(7,2) -> log_softmax.
// R3: 4 rows/thread (two f32x2-packed row pairs), duplicated weights in shared
// (one LDS.128 = two packed broadcast operands), packed mul/add around MUFU.EX2.

constexpr int H       = 7;
constexpr int NMID    = 19;
constexpr int THREADS = 256;
constexpr int LSTRIDE = 56;   // float2 slots per layer: 7 i * (7 w + 1 bias)

typedef unsigned long long u64;

__device__ __forceinline__ u64 pack2(float lo, float hi) {
    u64 r; asm("mov.b64 %0, {%1, %2};" : "=l"(r) : "f"(lo), "f"(hi)); return r;
}
__device__ __forceinline__ void unpack2(u64 v, float& lo, float& hi) {
    asm("mov.b64 {%0, %1}, %2;" : "=f"(lo), "=f"(hi) : "l"(v));
}
__device__ __forceinline__ u64 fma2(u64 a, u64 b, u64 c) {
    u64 d; asm("fma.rn.f32x2 %0, %1, %2, %3;" : "=l"(d) : "l"(a), "l"(b), "l"(c));
    return d;
}
__device__ __forceinline__ u64 mul2(u64 a, u64 b) {
    u64 d; asm("mul.rn.f32x2 %0, %1, %2;" : "=l"(d) : "l"(a), "l"(b)); return d;
}
__device__ __forceinline__ u64 add2(u64 a, u64 b) {
    u64 d; asm("add.rn.f32x2 %0, %1, %2;" : "=l"(d) : "l"(a), "l"(b)); return d;
}
__device__ __forceinline__ float ex2f(float x) {
    float r; asm("ex2.approx.f32 %0, %1;" : "=f"(r) : "f"(x)); return r;
}

// Packed ELU: v>0 ? v : exp(v)-1.  Packed MUL (x*log2e) + 2x MUFU + packed ADD(-1),
// scalar compare/select per half (alu pipe, not the fma bottleneck).
__device__ __forceinline__ u64 elu2(u64 v) {
    const u64 LOG2E2 = pack2(1.4426950408889634f, 1.4426950408889634f);
    const u64 NEG1_2 = pack2(-1.0f, -1.0f);
    u64 t = mul2(v, LOG2E2);
    float tlo, thi; unpack2(t, tlo, thi);
    u64 e   = pack2(ex2f(tlo), ex2f(thi));
    u64 em1 = add2(e, NEG1_2);
    float vlo, vhi; unpack2(v, vlo, vhi);
    float mlo, mhi; unpack2(em1, mlo, mhi);
    float rlo = vlo > 0.0f ? vlo : mlo;
    float rhi = vhi > 0.0f ? vhi : mhi;
    return pack2(rlo, rhi);
}

__global__ void __launch_bounds__(THREADS, 3)
net0_kernel(const float* __restrict__ x,
            const float* __restrict__ W1, const float* __restrict__ b1,
            const float* __restrict__ Wm, const float* __restrict__ bm,
            const float* __restrict__ Wo, const float* __restrict__ bo,
            float* __restrict__ out, int nQuads)
{
    __shared__ __align__(16) float2 sFc1[H * 4];         // per i: {w0d, w1d, bd, pad}
    __shared__ __align__(16) float2 sMid[NMID * LSTRIDE];
    __shared__ __align__(16) float2 sFcO[2 * 8];         // per r: 7 wd + bias d

    for (int idx = threadIdx.x; idx < H * 4; idx += THREADS) {
        int i = idx >> 2, k = idx & 3;
        float v = (k < 2) ? W1[i * 2 + k] : (k == 2 ? b1[i] : 0.0f);
        sFc1[idx] = make_float2(v, v);
    }
    for (int idx = threadIdx.x; idx < NMID * H * 8; idx += THREADS) {
        int l = idx / (H * 8);
        int r = idx - l * (H * 8);
        int i = r >> 3, k = r & 7;
        float v = (k < 7) ? Wm[(l * H + i) * H + k] : bm[l * H + i];
        sMid[l * LSTRIDE + i * 8 + k] = make_float2(v, v);
    }
    for (int idx = threadIdx.x; idx < 16; idx += THREADS) {
        int r = idx >> 3, k = idx & 7;
        float v = (k < 7) ? Wo[r * H + k] : bo[r];
        sFcO[idx] = make_float2(v, v);
    }
    __syncthreads();

    int q = blockIdx.x * THREADS + threadIdx.x;   // 4 rows per thread
    if (q >= nQuads) return;

    float4 xa = reinterpret_cast<const float4*>(x)[2 * q + 0];  // rows 4q,4q+1
    float4 xb = reinterpret_cast<const float4*>(x)[2 * q + 1];  // rows 4q+2,4q+3
    u64 xa0 = pack2(xa.x, xa.z), xa1 = pack2(xa.y, xa.w);
    u64 xb0 = pack2(xb.x, xb.z), xb1 = pack2(xb.y, xb.w);

    u64 ha[H], hb[H];

    // ---- fc1 + ELU ----
#pragma unroll
    for (int i = 0; i < H; i++) {
        const ulonglong2* p = reinterpret_cast<const ulonglong2*>(&sFc1[i * 4]);
        ulonglong2 a = p[0];      // {w0 dup, w1 dup}
        ulonglong2 b = p[1];      // {bias dup, pad}
        ha[i] = elu2(fma2(a.x, xa0, fma2(a.y, xa1, b.x)));
        hb[i] = elu2(fma2(a.x, xb0, fma2(a.y, xb1, b.x)));
    }

    // ---- fc2..fc20 : rolled layer loop ----
#pragma unroll 1
    for (int l = 0; l < NMID; l++) {
        const ulonglong2* base =
            reinterpret_cast<const ulonglong2*>(&sMid[l * LSTRIDE]);
        u64 hna[H], hnb[H];
#pragma unroll
        for (int i = 0; i < H; i++) {
            ulonglong2 q0 = base[i * 4 + 0];   // w0,w1
            ulonglong2 q1 = base[i * 4 + 1];   // w2,w3
            ulonglong2 q2 = base[i * 4 + 2];   // w4,w5
            ulonglong2 q3 = base[i * 4 + 3];   // w6,bias
            u64 acca = q3.y, accb = q3.y;
            acca = fma2(q0.x, ha[0], acca);  accb = fma2(q0.x, hb[0], accb);
            acca = fma2(q0.y, ha[1], acca);  accb = fma2(q0.y, hb[1], accb);
            acca = fma2(q1.x, ha[2], acca);  accb = fma2(q1.x, hb[2], accb);
            acca = fma2(q1.y, ha[3], acca);  accb = fma2(q1.y, hb[3], accb);
            acca = fma2(q2.x, ha[4], acca);  accb = fma2(q2.x, hb[4], accb);
            acca = fma2(q2.y, ha[5], acca);  accb = fma2(q2.y, hb[5], accb);
            acca = fma2(q3.x, ha[6], acca);  accb = fma2(q3.x, hb[6], accb);
            hna[i] = acca;  hnb[i] = accb;
        }
#pragma unroll
        for (int i = 0; i < H; i++) { ha[i] = elu2(hna[i]); hb[i] = elu2(hnb[i]); }
    }

    // ---- fc21 (2 logits per row) ----
    u64 lpa[2], lpb[2];
#pragma unroll
    for (int r = 0; r < 2; r++) {
        const ulonglong2* p = reinterpret_cast<const ulonglong2*>(&sFcO[r * 8]);
        ulonglong2 q0 = p[0], q1 = p[1], q2 = p[2], q3 = p[3];
        u64 acca = q3.y, accb = q3.y;
        acca = fma2(q0.x, ha[0], acca);  accb = fma2(q0.x, hb[0], accb);
        acca = fma2(q0.y, ha[1], acca);  accb = fma2(q0.y, hb[1], accb);
        acca = fma2(q1.x, ha[2], acca);  accb = fma2(q1.x, hb[2], accb);
        acca = fma2(q1.y, ha[3], acca);  accb = fma2(q1.y, hb[3], accb);
        acca = fma2(q2.x, ha[4], acca);  accb = fma2(q2.x, hb[4], accb);
        acca = fma2(q2.y, ha[5], acca);  accb = fma2(q2.y, hb[5], accb);
        acca = fma2(q3.x, ha[6], acca);  accb = fma2(q3.x, hb[6], accb);
        lpa[r] = acca;  lpb[r] = accb;
    }

    // log_softmax over 2 classes, per row
    float a0lo, a0hi, a1lo, a1hi, b0lo, b0hi, b1lo, b1hi;
    unpack2(lpa[0], a0lo, a0hi);  unpack2(lpa[1], a1lo, a1hi);
    unpack2(lpb[0], b0lo, b0hi);  unpack2(lpb[1], b1lo, b1hi);

    auto lsm = [](float l0, float l1, float& o0, float& o1) {
        float m   = fmaxf(l0, l1);
        float s   = ex2f((l0 - m) * 1.4426950408889634f)
                  + ex2f((l1 - m) * 1.4426950408889634f);
        float lse = m + __logf(s);
        o0 = l0 - lse;  o1 = l1 - lse;
    };

    float4 oa, ob;
    lsm(a0lo, a1lo, oa.x, oa.y);   // row 4q
    lsm(a0hi, a1hi, oa.z, oa.w);   // row 4q+1
    lsm(b0lo, b1lo, ob.x, ob.y);   // row 4q+2
    lsm(b0hi, b1hi, ob.z, ob.w);   // row 4q+3

    reinterpret_cast<float4*>(out)[2 * q + 0] = oa;
    reinterpret_cast<float4*>(out)[2 * q + 1] = ob;
}

extern "C" void kernel_launch(void* const* d_in, const int* in_sizes, int n_in,
                              void* d_out, int out_size)
{
    const float* x  = (const float*)d_in[0];
    const float* W1 = (const float*)d_in[1];
    const float* b1 = (const float*)d_in[2];
    const float* Wm = (const float*)d_in[3];
    const float* bm = (const float*)d_in[4];
    const float* Wo = (const float*)d_in[5];
    const float* bo = (const float*)d_in[6];
    float* out = (float*)d_out;

    int nQuads = in_sizes[0] / 8;   // x is [B,2]; 4 rows per thread
    int grid = (nQuads + THREADS - 1) / THREADS;
    net0_kernel<<<grid, THREADS>>>(x, W1, b1, Wm, bm, Wo, bo, out, nQuads);
}

// round 5
// speedup vs baseline: 1.7754x; 1.0002x over previous
#include <cuda_runtime.h>

// Net0: x[B,2] -> fc1(2,7)+ELU -> 19x fc(7,7)+ELU -> fc(7,2) -> log_softmax.
// R5: 4 rows/thread, FFMA2 matmuls; ELU carried as g = elu(z)+1:
//     g = fmax(z,0) + fmin(exp2(z*log2e),1)   (scalar FMNMX on alu pipe)
// with the -1 folded into the next layer's bias (b' = b - rowsum(W)).

constexpr int H       = 7;
constexpr int NMID    = 19;
constexpr int THREADS = 256;
constexpr int LSTRIDE = 56;   // float2 slots per layer: 7 i * (7 w + 1 bias)

typedef unsigned long long u64;

__device__ __forceinline__ u64 pack2(float lo, float hi) {
    u64 r; asm("mov.b64 %0, {%1, %2};" : "=l"(r) : "f"(lo), "f"(hi)); return r;
}
__device__ __forceinline__ void unpack2(u64 v, float& lo, float& hi) {
    asm("mov.b64 {%0, %1}, %2;" : "=f"(lo), "=f"(hi) : "l"(v));
}
__device__ __forceinline__ u64 fma2(u64 a, u64 b, u64 c) {
    u64 d; asm("fma.rn.f32x2 %0, %1, %2, %3;" : "=l"(d) : "l"(a), "l"(b), "l"(c));
    return d;
}
__device__ __forceinline__ u64 mul2(u64 a, u64 b) {
    u64 d; asm("mul.rn.f32x2 %0, %1, %2;" : "=l"(d) : "l"(a), "l"(b)); return d;
}
__device__ __forceinline__ float ex2f(float x) {
    float r; asm("ex2.approx.f32 %0, %1;" : "=f"(r) : "f"(x)); return r;
}

// g = elu(z) + 1 = max(z,0) + min(exp(z),1).
// mul2 (fma pipe) + 2x MUFU + 4x FMNMX (alu pipe) + 2x FADD (fma pipe).
__device__ __forceinline__ u64 elu2g(u64 z, u64 cLog2e) {
    u64 t = mul2(z, cLog2e);
    float tl, th; unpack2(t, tl, th);
    float el = ex2f(tl), eh = ex2f(th);
    float zl, zh; unpack2(z, zl, zh);
    float rl = fmaxf(zl, 0.0f) + fminf(el, 1.0f);
    float rh = fmaxf(zh, 0.0f) + fminf(eh, 1.0f);
    return pack2(rl, rh);
}

__global__ void __launch_bounds__(THREADS, 3)
net0_kernel(const float* __restrict__ x,
            const float* __restrict__ W1, const float* __restrict__ b1,
            const float* __restrict__ Wm, const float* __restrict__ bm,
            const float* __restrict__ Wo, const float* __restrict__ bo,
            float* __restrict__ out, int nQuads)
{
    __shared__ __align__(16) float2 sFc1[H * 4];         // per i: {w0d, w1d, bd, pad}
    __shared__ __align__(16) float2 sMid[NMID * LSTRIDE];
    __shared__ __align__(16) float2 sFcO[2 * 8];         // per r: 7 wd + bias' d

    // fc1: raw bias (its input x is not an ELU-g).
    for (int idx = threadIdx.x; idx < H * 4; idx += THREADS) {
        int i = idx >> 2, k = idx & 3;
        float v = (k < 2) ? W1[i * 2 + k] : (k == 2 ? b1[i] : 0.0f);
        sFc1[idx] = make_float2(v, v);
    }
    // mid layers: adjusted bias b' = b - rowsum(W) (consumes g = h+1).
    for (int idx = threadIdx.x; idx < NMID * H * 8; idx += THREADS) {
        int l = idx / (H * 8);
        int r = idx - l * (H * 8);
        int i = r >> 3, k = r & 7;
        float v;
        if (k < 7) {
            v = Wm[(l * H + i) * H + k];
        } else {
            float s = 0.0f;
            for (int j = 0; j < H; j++) s += Wm[(l * H + i) * H + j];
            v = bm[l * H + i] - s;
        }
        sMid[l * LSTRIDE + i * 8 + k] = make_float2(v, v);
    }
    // fc21: adjusted bias bo' = bo - rowsum(Wo).
    for (int idx = threadIdx.x; idx < 16; idx += THREADS) {
        int r = idx >> 3, k = idx & 7;
        float v;
        if (k < 7) {
            v = Wo[r * H + k];
        } else {
            float s = 0.0f;
            for (int j = 0; j < H; j++) s += Wo[r * H + j];
            v = bo[r] - s;
        }
        sFcO[idx] = make_float2(v, v);
    }
    __syncthreads();

    const u64 cLog2e = pack2(1.4426950408889634f, 1.4426950408889634f);

    int q = blockIdx.x * THREADS + threadIdx.x;   // 4 rows per thread
    if (q >= nQuads) return;

    float4 xa = reinterpret_cast<const float4*>(x)[2 * q + 0];  // rows 4q,4q+1
    float4 xb = reinterpret_cast<const float4*>(x)[2 * q + 1];  // rows 4q+2,4q+3
    u64 xa0 = pack2(xa.x, xa.z), xa1 = pack2(xa.y, xa.w);
    u64 xb0 = pack2(xb.x, xb.z), xb1 = pack2(xb.y, xb.w);

    u64 ha[H], hb[H];   // carry g = elu(z)+1

    // ---- fc1 + ELU(g) ----
#pragma unroll
    for (int i = 0; i < H; i++) {
        const ulonglong2* p = reinterpret_cast<const ulonglong2*>(&sFc1[i * 4]);
        ulonglong2 a = p[0];      // {w0 dup, w1 dup}
        ulonglong2 b = p[1];      // {bias dup, pad}
        ha[i] = elu2g(fma2(a.x, xa0, fma2(a.y, xa1, b.x)), cLog2e);
        hb[i] = elu2g(fma2(a.x, xb0, fma2(a.y, xb1, b.x)), cLog2e);
    }

    // ---- fc2..fc20 : rolled layer loop ----
#pragma unroll 1
    for (int l = 0; l < NMID; l++) {
        const ulonglong2* base =
            reinterpret_cast<const ulonglong2*>(&sMid[l * LSTRIDE]);
        u64 hna[H], hnb[H];
#pragma unroll
        for (int i = 0; i < H; i++) {
            ulonglong2 q0 = base[i * 4 + 0];   // w0,w1
            ulonglong2 q1 = base[i * 4 + 1];   // w2,w3
            ulonglong2 q2 = base[i * 4 + 2];   // w4,w5
            ulonglong2 q3 = base[i * 4 + 3];   // w6,bias'
            u64 acca = q3.y, accb = q3.y;
            acca = fma2(q0.x, ha[0], acca);  accb = fma2(q0.x, hb[0], accb);
            acca = fma2(q0.y, ha[1], acca);  accb = fma2(q0.y, hb[1], accb);
            acca = fma2(q1.x, ha[2], acca);  accb = fma2(q1.x, hb[2], accb);
            acca = fma2(q1.y, ha[3], acca);  accb = fma2(q1.y, hb[3], accb);
            acca = fma2(q2.x, ha[4], acca);  accb = fma2(q2.x, hb[4], accb);
            acca = fma2(q2.y, ha[5], acca);  accb = fma2(q2.y, hb[5], accb);
            acca = fma2(q3.x, ha[6], acca);  accb = fma2(q3.x, hb[6], accb);
            hna[i] = acca;  hnb[i] = accb;
        }
#pragma unroll
        for (int i = 0; i < H; i++) {
            ha[i] = elu2g(hna[i], cLog2e);
            hb[i] = elu2g(hnb[i], cLog2e);
        }
    }

    // ---- fc21 (2 logits per row, adjusted bias) ----
    u64 lpa[2], lpb[2];
#pragma unroll
    for (int r = 0; r < 2; r++) {
        const ulonglong2* p = reinterpret_cast<const ulonglong2*>(&sFcO[r * 8]);
        ulonglong2 q0 = p[0], q1 = p[1], q2 = p[2], q3 = p[3];
        u64 acca = q3.y, accb = q3.y;
        acca = fma2(q0.x, ha[0], acca);  accb = fma2(q0.x, hb[0], accb);
        acca = fma2(q0.y, ha[1], acca);  accb = fma2(q0.y, hb[1], accb);
        acca = fma2(q1.x, ha[2], acca);  accb = fma2(q1.x, hb[2], accb);
        acca = fma2(q1.y, ha[3], acca);  accb = fma2(q1.y, hb[3], accb);
        acca = fma2(q2.x, ha[4], acca);  accb = fma2(q2.x, hb[4], accb);
        acca = fma2(q2.y, ha[5], acca);  accb = fma2(q2.y, hb[5], accb);
        acca = fma2(q3.x, ha[6], acca);  accb = fma2(q3.x, hb[6], accb);
        lpa[r] = acca;  lpb[r] = accb;
    }

    float a0lo, a0hi, a1lo, a1hi, b0lo, b0hi, b1lo, b1hi;
    unpack2(lpa[0], a0lo, a0hi);  unpack2(lpa[1], a1lo, a1hi);
    unpack2(lpb[0], b0lo, b0hi);  unpack2(lpb[1], b1lo, b1hi);

    auto lsm = [](float l0, float l1, float& o0, float& o1) {
        float m   = fmaxf(l0, l1);
        float s   = ex2f((l0 - m) * 1.4426950408889634f)
                  + ex2f((l1 - m) * 1.4426950408889634f);
        float lse = m + __logf(s);
        o0 = l0 - lse;  o1 = l1 - lse;
    };

    float4 oa, ob;
    lsm(a0lo, a1lo, oa.x, oa.y);   // row 4q
    lsm(a0hi, a1hi, oa.z, oa.w);   // row 4q+1
    lsm(b0lo, b1lo, ob.x, ob.y);   // row 4q+2
    lsm(b0hi, b1hi, ob.z, ob.w);   // row 4q+3

    reinterpret_cast<float4*>(out)[2 * q + 0] = oa;
    reinterpret_cast<float4*>(out)[2 * q + 1] = ob;
}

extern "C" void kernel_launch(void* const* d_in, const int* in_sizes, int n_in,
                              void* d_out, int out_size)
{
    const float* x  = (const float*)d_in[0];
    const float* W1 = (const float*)d_in[1];
    const float* b1 = (const float*)d_in[2];
    const float* Wm = (const float*)d_in[3];
    const float* bm = (const float*)d_in[4];
    const float* Wo = (const float*)d_in[5];
    const float* bo = (const float*)d_in[6];
    float* out = (float*)d_out;

    int nQuads = in_sizes[0] / 8;   // x is [B,2]; 4 rows per thread
    int grid = (nQuads + THREADS - 1) / THREADS;
    net0_kernel<<<grid, THREADS>>>(x, W1, b1, Wm, bm, Wo, bo, out, nQuads);
}